// round 2
// baseline (speedup 1.0000x reference)
#include <cuda_runtime.h>
#include <math.h>

#define HH 128
#define WW 128
#define NMAX 2

// ---- scratch (no allocations allowed) ----
__device__ float d_gw1f[256 * 256 * 9];
__device__ float d_seg_mid[NMAX * 32 * HH * WW];
__device__ float d_seg[NMAX * 64 * HH * WW];
__device__ float d_g[NMAX * 256 * HH * WW];
__device__ float d_wts[NMAX * 144 * HH * WW];

// Fold gw1 (256, 512, 3, 3) over the redundant concat: gw1f[o][i][t] = gw1[o][i][t] + gw1[o][i+256][t]
__global__ void fold_gw1_kernel(const float* __restrict__ gw1) {
    int i = blockIdx.x * 256 + threadIdx.x;
    if (i < 256 * 256 * 9) {
        int o = i / (256 * 9);
        int rest = i - o * 256 * 9;
        int ci = rest / 9;
        int t = rest - ci * 9;
        d_gw1f[i] = gw1[(o * 512 + ci) * 9 + t] + gw1[(o * 512 + ci + 256) * 9 + t];
    }
}

// Register-blocked direct 3x3 conv, pad=1.
// Block: 256 threads = 32 wide x 8 rows; each thread computes 4 rows (stride 8) x 8 output channels.
// Tile: 32x32 output pixels, 8 output channels per block.
template <int CIN, int COUT, bool RELU>
__launch_bounds__(256)
__global__ void conv3x3_kernel(const float* __restrict__ in, const float* __restrict__ w,
                               const float* __restrict__ bias, float* __restrict__ out) {
    constexpr int OCB = 8, CIB = 4;
    __shared__ float s_in[CIB][34][34];
    __shared__ float s_w[CIB][9][OCB];

    const int wx = threadIdx.x & 31;
    const int yy = threadIdx.x >> 5;  // 0..7
    const int x0 = blockIdx.x * 32;
    const int y0 = blockIdx.y * 32;
    const int zb = blockIdx.z;
    const int n = zb / (COUT / OCB);
    const int oc0 = (zb - n * (COUT / OCB)) * OCB;
    const float* inN = in + (size_t)n * CIN * HH * WW;

    float acc[4][OCB];
#pragma unroll
    for (int r = 0; r < 4; r++)
#pragma unroll
        for (int o = 0; o < OCB; o++) acc[r][o] = 0.f;

    for (int ci0 = 0; ci0 < CIN; ci0 += CIB) {
        __syncthreads();
        // stage input halo tile
        for (int idx = threadIdx.x; idx < CIB * 34 * 34; idx += 256) {
            int ci = idx / (34 * 34);
            int rem = idx - ci * 34 * 34;
            int r = rem / 34;
            int c = rem - r * 34;
            int gy = y0 + r - 1, gx = x0 + c - 1;
            float v = 0.f;
            if (gy >= 0 && gy < HH && gx >= 0 && gx < WW)
                v = inN[((size_t)(ci0 + ci) * HH + gy) * WW + gx];
            s_in[ci][r][c] = v;
        }
        // stage weights, layout [ci][tap][oc] for broadcast reads
        for (int idx = threadIdx.x; idx < CIB * 9 * OCB; idx += 256) {
            int oc = idx & (OCB - 1);
            int t = (idx / OCB) % 9;
            int ci = idx / (OCB * 9);
            s_w[ci][t][oc] = w[((size_t)(oc0 + oc) * CIN + ci0 + ci) * 9 + t];
        }
        __syncthreads();
#pragma unroll
        for (int ci = 0; ci < CIB; ci++) {
#pragma unroll
            for (int t = 0; t < 9; t++) {
                const int dy = t / 3, dx = t % 3;
                float wr[OCB];
#pragma unroll
                for (int o = 0; o < OCB; o++) wr[o] = s_w[ci][t][o];
#pragma unroll
                for (int r = 0; r < 4; r++) {
                    float iv = s_in[ci][yy + r * 8 + dy][wx + dx];
#pragma unroll
                    for (int o = 0; o < OCB; o++)
                        acc[r][o] = fmaf(iv, wr[o], acc[r][o]);
                }
            }
        }
    }
#pragma unroll
    for (int o = 0; o < OCB; o++) {
        float bv = bias[oc0 + o];
#pragma unroll
        for (int r = 0; r < 4; r++) {
            float v = acc[r][o] + bv;
            if (RELU) v = fmaxf(v, 0.f);
            out[((size_t)(n * COUT + oc0 + o) * HH + y0 + yy + r * 8) * WW + x0 + wx] = v;
        }
    }
}

// 1x1 conv (pointwise GEMM), same blocking scheme (no halo).
template <int CIN, int COUT>
__launch_bounds__(256)
__global__ void conv1x1_kernel(const float* __restrict__ in, const float* __restrict__ w,
                               const float* __restrict__ bias, float* __restrict__ out) {
    constexpr int OCB = 8, CIB = 8;
    __shared__ float s_in[CIB][32][32];
    __shared__ float s_w[CIB][OCB];

    const int wx = threadIdx.x & 31;
    const int yy = threadIdx.x >> 5;
    const int x0 = blockIdx.x * 32;
    const int y0 = blockIdx.y * 32;
    const int zb = blockIdx.z;
    const int n = zb / (COUT / OCB);
    const int oc0 = (zb - n * (COUT / OCB)) * OCB;
    const float* inN = in + (size_t)n * CIN * HH * WW;

    float acc[4][OCB];
#pragma unroll
    for (int r = 0; r < 4; r++)
#pragma unroll
        for (int o = 0; o < OCB; o++) acc[r][o] = 0.f;

    for (int ci0 = 0; ci0 < CIN; ci0 += CIB) {
        __syncthreads();
        for (int idx = threadIdx.x; idx < CIB * 32 * 32; idx += 256) {
            int ci = idx >> 10;
            int rem = idx & 1023;
            int r = rem >> 5;
            int c = rem & 31;
            s_in[ci][r][c] = inN[((size_t)(ci0 + ci) * HH + y0 + r) * WW + x0 + c];
        }
        if (threadIdx.x < CIB * OCB) {
            int oc = threadIdx.x & (OCB - 1);
            int ci = threadIdx.x / OCB;
            s_w[ci][oc] = w[(size_t)(oc0 + oc) * CIN + ci0 + ci];
        }
        __syncthreads();
#pragma unroll
        for (int ci = 0; ci < CIB; ci++) {
            float wr[OCB];
#pragma unroll
            for (int o = 0; o < OCB; o++) wr[o] = s_w[ci][o];
#pragma unroll
            for (int r = 0; r < 4; r++) {
                float iv = s_in[ci][yy + r * 8][wx];
#pragma unroll
                for (int o = 0; o < OCB; o++)
                    acc[r][o] = fmaf(iv, wr[o], acc[r][o]);
            }
        }
    }
#pragma unroll
    for (int o = 0; o < OCB; o++) {
        float bv = bias[oc0 + o];
#pragma unroll
        for (int r = 0; r < 4; r++) {
            out[((size_t)(n * COUT + oc0 + o) * HH + y0 + yy + r * 8) * WW + x0 + wx] =
                acc[r][o] + bv;
        }
    }
}

// Fused: softmax over the 9-tap window + convex combination over unfolded seg + 4x pixel shuffle.
// Block: 128 threads = (a 0..3) x (wl 0..31). One block handles (n, h, 32 w-positions).
// Channel layout of wts: c144 = k*16 + a*4 + b.
__launch_bounds__(128)
__global__ void combine_kernel(const float* __restrict__ wts, const float* __restrict__ seg,
                               float* __restrict__ out) {
    __shared__ float s_w[144][32];
    __shared__ float s_seg[3][36];
    const int tid = threadIdx.x;
    const int n = blockIdx.z, h = blockIdx.y, w0 = blockIdx.x * 32;

    // stage raw guidance logits for this (h, w-tile)
    for (int idx = tid; idx < 144 * 32; idx += 128) {
        int ch = idx >> 5, wl = idx & 31;
        s_w[ch][wl] = wts[((size_t)(n * 144 + ch) * HH + h) * WW + w0 + wl];
    }
    __syncthreads();
    // softmax over k (stride-16 channels) for each (ab, wl): 512 tasks
    for (int t = tid; t < 512; t += 128) {
        int wl = t & 31, ab = t >> 5;
        float v[9];
        float m = -1e30f;
#pragma unroll
        for (int k = 0; k < 9; k++) { v[k] = s_w[k * 16 + ab][wl]; m = fmaxf(m, v[k]); }
        float s = 0.f;
#pragma unroll
        for (int k = 0; k < 9; k++) { v[k] = expf(v[k] - m); s += v[k]; }
        float inv = 1.f / s;
#pragma unroll
        for (int k = 0; k < 9; k++) s_w[k * 16 + ab][wl] = v[k] * inv;
    }
    __syncthreads();

    const int wl = tid & 31, a = tid >> 5;
    float sw[4][9];
#pragma unroll
    for (int b = 0; b < 4; b++)
#pragma unroll
        for (int k = 0; k < 9; k++)
            sw[b][k] = s_w[k * 16 + a * 4 + b][wl];

    for (int c = 0; c < 64; c++) {
        __syncthreads();
        // stage seg rows h-1..h+1, cols w0-1..w0+32 for this channel
        for (int idx = tid; idx < 3 * 34; idx += 128) {
            int r = idx / 34, cc = idx - r * 34;
            int gy = h - 1 + r, gx = w0 - 1 + cc;
            float v = 0.f;
            if (gy >= 0 && gy < HH && gx >= 0 && gx < WW)
                v = seg[((size_t)(n * 64 + c) * HH + gy) * WW + gx];
            s_seg[r][cc] = v;
        }
        __syncthreads();
        float p[9];
#pragma unroll
        for (int dy = 0; dy < 3; dy++)
#pragma unroll
            for (int dx = 0; dx < 3; dx++)
                p[dy * 3 + dx] = s_seg[dy][wl + dx];
        float4 ov;
        float* po = (float*)&ov;
#pragma unroll
        for (int b = 0; b < 4; b++) {
            float acc = 0.f;
#pragma unroll
            for (int k = 0; k < 9; k++) acc = fmaf(sw[b][k], p[k], acc);
            po[b] = acc;
        }
        size_t off = (((size_t)(n * 64 + c) * (4 * HH) + 4 * h + a) * (size_t)(4 * WW)) +
                     4 * (w0 + wl);
        *reinterpret_cast<float4*>(out + off) = ov;
    }
}

extern "C" void kernel_launch(void* const* d_in, const int* in_sizes, int n_in,
                              void* d_out, int out_size) {
    const float* x   = (const float*)d_in[0];
    const float* f1  = (const float*)d_in[1];
    const float* w1  = (const float*)d_in[2];
    const float* b1  = (const float*)d_in[3];
    const float* w2  = (const float*)d_in[4];
    const float* b2  = (const float*)d_in[5];
    const float* gw1 = (const float*)d_in[6];
    const float* gb1 = (const float*)d_in[7];
    const float* gw2 = (const float*)d_in[8];
    const float* gb2 = (const float*)d_in[9];
    float* out = (float*)d_out;

    const int N = in_sizes[0] / (64 * HH * WW);

    float *p_gw1f = nullptr, *p_segmid = nullptr, *p_seg = nullptr, *p_g = nullptr,
          *p_wts = nullptr;
    cudaGetSymbolAddress((void**)&p_gw1f, d_gw1f);
    cudaGetSymbolAddress((void**)&p_segmid, d_seg_mid);
    cudaGetSymbolAddress((void**)&p_seg, d_seg);
    cudaGetSymbolAddress((void**)&p_g, d_g);
    cudaGetSymbolAddress((void**)&p_wts, d_wts);

    // 1. fold redundant-concat weights: 512 -> 256 input channels
    fold_gw1_kernel<<<(256 * 256 * 9 + 255) / 256, 256>>>(gw1);
    // 2. seg branch: conv3x3 64->32 + relu, conv3x3 32->64
    conv3x3_kernel<64, 32, true><<<dim3(WW / 32, HH / 32, N * (32 / 8)), 256>>>(x, w1, b1, p_segmid);
    conv3x3_kernel<32, 64, false><<<dim3(WW / 32, HH / 32, N * (64 / 8)), 256>>>(p_segmid, w2, b2, p_seg);
    // 3. guidance: folded conv3x3 256->256 + relu
    conv3x3_kernel<256, 256, true><<<dim3(WW / 32, HH / 32, N * (256 / 8)), 256>>>(f1, p_gw1f, gb1, p_g);
    // 4. conv1x1 256->144 (raw softmax logits)
    conv1x1_kernel<256, 144><<<dim3(WW / 32, HH / 32, N * (144 / 8)), 256>>>(p_g, gw2, gb2, p_wts);
    // 5. softmax + convex combine + pixel shuffle
    combine_kernel<<<dim3(WW / 32, HH, N), 128>>>(p_wts, p_seg, out);
}

// round 4
// speedup vs baseline: 1.7653x; 1.7653x over previous
#include <cuda_runtime.h>
#include <math.h>

#define HH 128
#define WW 128
#define NMAX 2

// ---- scratch (no allocations allowed) ----
__device__ float d_gw1t[9 * 256 * 256];  // folded + transposed [tap][ci][oc], tf32-rounded
__device__ float d_seg_mid[NMAX * 32 * HH * WW];
__device__ float d_seg[NMAX * 64 * HH * WW];
__device__ float d_g[NMAX * 256 * HH * WW];
__device__ float d_wts[NMAX * 144 * HH * WW];

__device__ __forceinline__ unsigned f2tf32(float v) {
    unsigned u;
    asm("cvt.rna.tf32.f32 %0, %1;" : "=r"(u) : "f"(v));
    return u;
}

// Fold gw1 (256, 512, 3, 3) over the redundant concat AND transpose to [tap][ci][oc],
// rounding to tf32 once so the hot loop does no conversions on weights.
__global__ void fold_gw1_kernel(const float* __restrict__ gw1) {
    int i = blockIdx.x * 256 + threadIdx.x;
    if (i < 9 * 256 * 256) {
        int t = i / (256 * 256);
        int r = i - t * 256 * 256;
        int ci = r >> 8;
        int oc = r & 255;
        float v = gw1[(oc * 512 + ci) * 9 + t] + gw1[(oc * 512 + ci + 256) * 9 + t];
        d_gw1t[i] = __uint_as_float(f2tf32(v));
    }
}

// ===================== tf32 tensor-core implicit-GEMM guidance conv =====================
// D[pix, oc] = sum_{tap, ci} A[pix, (tap,ci)] * W[(tap,ci), oc], then +bias, relu.
// Block tile: M = 256 pixels (2 rows x 128 cols), N = 128 oc. K-chunk: 16 ci (all 9 taps).
// 8 warps = 4 (m) x 2 (n); warp tile 64 px x 64 oc = 4 m16-tiles x 8 n8-tiles.
#define KC 16
#define AP 18    // ci pitch of A tile (conflict-free a-frag LDS)
#define BP 136   // oc pitch of B tile (conflict-free b-frag LDS)
#define SB_FLOATS (9 * KC * BP)   // 19584
#define SA_FLOATS (4 * 130 * AP)  // 9360
#define GUID_SMEM ((SB_FLOATS + SA_FLOATS) * 4)  // 115776 bytes

__global__ void __launch_bounds__(256, 1)
guidance_mma_kernel(const float* __restrict__ f1, const float* __restrict__ wt,
                    const float* __restrict__ bias, float* __restrict__ out) {
    extern __shared__ float sm[];
    float* s_b = sm;              // [tap][ci][oc]  (t*KC+ci)*BP + oc
    float* s_a = sm + SB_FLOATS;  // [row 0..3][x 0..129][ci]  (r*130+x)*AP + ci

    const int tid = threadIdx.x;
    const int lane = tid & 31, wid = tid >> 5;
    const int g = lane >> 2, tg = lane & 3;
    const int warp_m = wid & 3, warp_n = wid >> 2;
    const int y0 = blockIdx.x * 2;       // two output rows per block
    const int oc0 = blockIdx.y * 128;    // oc half
    const int nimg = blockIdx.z;
    const int m0 = warp_m * 64;
    const int ry = m0 >> 7;              // which of the 2 output rows this warp handles
    const int xw = m0 & 127;             // warp's x offset
    const int n0 = warp_n * 64;

    const float* inN = f1 + (size_t)nimg * 256 * HH * WW;

    float acc[4][8][4];
#pragma unroll
    for (int mt = 0; mt < 4; mt++)
#pragma unroll
        for (int nt = 0; nt < 8; nt++)
#pragma unroll
            for (int c = 0; c < 4; c++) acc[mt][nt][c] = 0.f;

    for (int ci0 = 0; ci0 < 256; ci0 += KC) {
        __syncthreads();
        // stage A: 4 halo rows x 130 cols x 16 ci, tf32-rounded. Coalesced over x.
        for (int idx = tid; idx < KC * 4 * 130; idx += 256) {
            int x = idx % 130;
            int rr = idx / 130;
            int r = rr & 3;
            int ci = rr >> 2;
            int gy = y0 + r - 1, gx = x - 1;
            float v = 0.f;
            if (gy >= 0 && gy < HH && gx >= 0 && gx < WW)
                v = inN[((size_t)(ci0 + ci) * HH + gy) * WW + gx];
            s_a[(r * 130 + x) * AP + ci] = __uint_as_float(f2tf32(v));
        }
        // stage B: 9 taps x 16 ci x 128 oc (already tf32). Coalesced over oc.
        for (int idx = tid; idx < 9 * KC * 128; idx += 256) {
            int oc = idx & 127;
            int rest = idx >> 7;
            int ci = rest & 15;
            int t = rest >> 4;
            s_b[(t * KC + ci) * BP + oc] = wt[((size_t)t * 256 + ci0 + ci) * 256 + oc0 + oc];
        }
        __syncthreads();

#pragma unroll 1
        for (int t = 0; t < 9; t++) {
            const int dy = t / 3, dx = t - dy * 3;
            const float* sa_row = s_a + ((ry + dy) * 130 + dx) * AP;
            const float* sb_tap = s_b + t * KC * BP;
#pragma unroll
            for (int ks = 0; ks < 2; ks++) {
                const int kb = ks * 8;
                unsigned a[4][4];
#pragma unroll
                for (int mt = 0; mt < 4; mt++) {
                    const float* pa = sa_row + (xw + mt * 16 + g) * AP + kb + tg;
                    a[mt][0] = __float_as_uint(pa[0]);
                    a[mt][2] = __float_as_uint(pa[4]);
                    a[mt][1] = __float_as_uint(pa[8 * AP]);
                    a[mt][3] = __float_as_uint(pa[8 * AP + 4]);
                }
                unsigned b[8][2];
#pragma unroll
                for (int nt = 0; nt < 8; nt++) {
                    const float* pb = sb_tap + (kb + tg) * BP + n0 + nt * 8 + g;
                    b[nt][0] = __float_as_uint(pb[0]);
                    b[nt][1] = __float_as_uint(pb[4 * BP]);
                }
#pragma unroll
                for (int mt = 0; mt < 4; mt++)
#pragma unroll
                    for (int nt = 0; nt < 8; nt++) {
                        float* c = acc[mt][nt];
                        asm volatile(
                            "mma.sync.aligned.m16n8k8.row.col.f32.tf32.tf32.f32 "
                            "{%0,%1,%2,%3}, {%4,%5,%6,%7}, {%8,%9}, {%0,%1,%2,%3};"
                            : "+f"(c[0]), "+f"(c[1]), "+f"(c[2]), "+f"(c[3])
                            : "r"(a[mt][0]), "r"(a[mt][1]), "r"(a[mt][2]), "r"(a[mt][3]),
                              "r"(b[nt][0]), "r"(b[nt][1]));
                    }
            }
        }
    }

    // epilogue: +bias, relu, NCHW store
#pragma unroll
    for (int nt = 0; nt < 8; nt++) {
        const int oc_lo = oc0 + n0 + nt * 8 + 2 * tg;
        const float b0 = bias[oc_lo];
        const float b1 = bias[oc_lo + 1];
        size_t p0 = ((size_t)(nimg * 256 + oc_lo) * HH + (y0 + ry)) * WW;
        size_t p1 = p0 + (size_t)HH * WW;
#pragma unroll
        for (int mt = 0; mt < 4; mt++) {
            const int x = xw + mt * 16 + g;
            out[p0 + x]     = fmaxf(acc[mt][nt][0] + b0, 0.f);
            out[p1 + x]     = fmaxf(acc[mt][nt][1] + b1, 0.f);
            out[p0 + x + 8] = fmaxf(acc[mt][nt][2] + b0, 0.f);
            out[p1 + x + 8] = fmaxf(acc[mt][nt][3] + b1, 0.f);
        }
    }
}

// ===================== small fp32 direct convs (seg branch) =====================
template <int CIN, int COUT, bool RELU>
__launch_bounds__(256)
__global__ void conv3x3_kernel(const float* __restrict__ in, const float* __restrict__ w,
                               const float* __restrict__ bias, float* __restrict__ out) {
    constexpr int OCB = 8, CIB = 4;
    __shared__ float s_in[CIB][34][34];
    __shared__ float s_w[CIB][9][OCB];

    const int wx = threadIdx.x & 31;
    const int yy = threadIdx.x >> 5;
    const int x0 = blockIdx.x * 32;
    const int y0 = blockIdx.y * 32;
    const int zb = blockIdx.z;
    const int n = zb / (COUT / OCB);
    const int oc0 = (zb - n * (COUT / OCB)) * OCB;
    const float* inN = in + (size_t)n * CIN * HH * WW;

    float acc[4][OCB];
#pragma unroll
    for (int r = 0; r < 4; r++)
#pragma unroll
        for (int o = 0; o < OCB; o++) acc[r][o] = 0.f;

    for (int ci0 = 0; ci0 < CIN; ci0 += CIB) {
        __syncthreads();
        for (int idx = threadIdx.x; idx < CIB * 34 * 34; idx += 256) {
            int ci = idx / (34 * 34);
            int rem = idx - ci * 34 * 34;
            int r = rem / 34;
            int c = rem - r * 34;
            int gy = y0 + r - 1, gx = x0 + c - 1;
            float v = 0.f;
            if (gy >= 0 && gy < HH && gx >= 0 && gx < WW)
                v = inN[((size_t)(ci0 + ci) * HH + gy) * WW + gx];
            s_in[ci][r][c] = v;
        }
        for (int idx = threadIdx.x; idx < CIB * 9 * OCB; idx += 256) {
            int oc = idx & (OCB - 1);
            int t = (idx / OCB) % 9;
            int ci = idx / (OCB * 9);
            s_w[ci][t][oc] = w[((size_t)(oc0 + oc) * CIN + ci0 + ci) * 9 + t];
        }
        __syncthreads();
#pragma unroll
        for (int ci = 0; ci < CIB; ci++) {
#pragma unroll
            for (int t = 0; t < 9; t++) {
                const int dy = t / 3, dx = t % 3;
                float wr[OCB];
#pragma unroll
                for (int o = 0; o < OCB; o++) wr[o] = s_w[ci][t][o];
#pragma unroll
                for (int r = 0; r < 4; r++) {
                    float iv = s_in[ci][yy + r * 8 + dy][wx + dx];
#pragma unroll
                    for (int o = 0; o < OCB; o++)
                        acc[r][o] = fmaf(iv, wr[o], acc[r][o]);
                }
            }
        }
    }
#pragma unroll
    for (int o = 0; o < OCB; o++) {
        float bv = bias[oc0 + o];
#pragma unroll
        for (int r = 0; r < 4; r++) {
            float v = acc[r][o] + bv;
            if (RELU) v = fmaxf(v, 0.f);
            out[((size_t)(n * COUT + oc0 + o) * HH + y0 + yy + r * 8) * WW + x0 + wx] = v;
        }
    }
}

// 1x1 conv (pointwise), fp32.
template <int CIN, int COUT>
__launch_bounds__(256)
__global__ void conv1x1_kernel(const float* __restrict__ in, const float* __restrict__ w,
                               const float* __restrict__ bias, float* __restrict__ out) {
    constexpr int OCB = 8, CIB = 8;
    __shared__ float s_in[CIB][32][32];
    __shared__ float s_w[CIB][OCB];

    const int wx = threadIdx.x & 31;
    const int yy = threadIdx.x >> 5;
    const int x0 = blockIdx.x * 32;
    const int y0 = blockIdx.y * 32;
    const int zb = blockIdx.z;
    const int n = zb / (COUT / OCB);
    const int oc0 = (zb - n * (COUT / OCB)) * OCB;
    const float* inN = in + (size_t)n * CIN * HH * WW;

    float acc[4][OCB];
#pragma unroll
    for (int r = 0; r < 4; r++)
#pragma unroll
        for (int o = 0; o < OCB; o++) acc[r][o] = 0.f;

    for (int ci0 = 0; ci0 < CIN; ci0 += CIB) {
        __syncthreads();
        for (int idx = threadIdx.x; idx < CIB * 32 * 32; idx += 256) {
            int ci = idx >> 10;
            int rem = idx & 1023;
            int r = rem >> 5;
            int c = rem & 31;
            s_in[ci][r][c] = inN[((size_t)(ci0 + ci) * HH + y0 + r) * WW + x0 + c];
        }
        if (threadIdx.x < CIB * OCB) {
            int oc = threadIdx.x & (OCB - 1);
            int ci = threadIdx.x / OCB;
            s_w[ci][oc] = w[(size_t)(oc0 + oc) * CIN + ci0 + ci];
        }
        __syncthreads();
#pragma unroll
        for (int ci = 0; ci < CIB; ci++) {
            float wr[OCB];
#pragma unroll
            for (int o = 0; o < OCB; o++) wr[o] = s_w[ci][o];
#pragma unroll
            for (int r = 0; r < 4; r++) {
                float iv = s_in[ci][yy + r * 8][wx];
#pragma unroll
                for (int o = 0; o < OCB; o++)
                    acc[r][o] = fmaf(iv, wr[o], acc[r][o]);
            }
        }
    }
#pragma unroll
    for (int o = 0; o < OCB; o++) {
        float bv = bias[oc0 + o];
#pragma unroll
        for (int r = 0; r < 4; r++) {
            out[((size_t)(n * COUT + oc0 + o) * HH + y0 + yy + r * 8) * WW + x0 + wx] =
                acc[r][o] + bv;
        }
    }
}

// Fused: softmax over 9-tap window + convex combination + 4x pixel shuffle.
__launch_bounds__(128)
__global__ void combine_kernel(const float* __restrict__ wts, const float* __restrict__ seg,
                               float* __restrict__ out) {
    __shared__ float s_w[144][32];
    __shared__ float s_seg[3][36];
    const int tid = threadIdx.x;
    const int n = blockIdx.z, h = blockIdx.y, w0 = blockIdx.x * 32;

    for (int idx = tid; idx < 144 * 32; idx += 128) {
        int ch = idx >> 5, wl = idx & 31;
        s_w[ch][wl] = wts[((size_t)(n * 144 + ch) * HH + h) * WW + w0 + wl];
    }
    __syncthreads();
    for (int t = tid; t < 512; t += 128) {
        int wl = t & 31, ab = t >> 5;
        float v[9];
        float m = -1e30f;
#pragma unroll
        for (int k = 0; k < 9; k++) { v[k] = s_w[k * 16 + ab][wl]; m = fmaxf(m, v[k]); }
        float s = 0.f;
#pragma unroll
        for (int k = 0; k < 9; k++) { v[k] = expf(v[k] - m); s += v[k]; }
        float inv = 1.f / s;
#pragma unroll
        for (int k = 0; k < 9; k++) s_w[k * 16 + ab][wl] = v[k] * inv;
    }
    __syncthreads();

    const int wl = tid & 31, a = tid >> 5;
    float sw[4][9];
#pragma unroll
    for (int b = 0; b < 4; b++)
#pragma unroll
        for (int k = 0; k < 9; k++)
            sw[b][k] = s_w[k * 16 + a * 4 + b][wl];

    for (int c = 0; c < 64; c++) {
        __syncthreads();
        for (int idx = tid; idx < 3 * 34; idx += 128) {
            int r = idx / 34, cc = idx - r * 34;
            int gy = h - 1 + r, gx = w0 - 1 + cc;
            float v = 0.f;
            if (gy >= 0 && gy < HH && gx >= 0 && gx < WW)
                v = seg[((size_t)(n * 64 + c) * HH + gy) * WW + gx];
            s_seg[r][cc] = v;
        }
        __syncthreads();
        float p[9];
#pragma unroll
        for (int dy = 0; dy < 3; dy++)
#pragma unroll
            for (int dx = 0; dx < 3; dx++)
                p[dy * 3 + dx] = s_seg[dy][wl + dx];
        float4 ov;
        float* po = (float*)&ov;
#pragma unroll
        for (int b = 0; b < 4; b++) {
            float acc2 = 0.f;
#pragma unroll
            for (int k = 0; k < 9; k++) acc2 = fmaf(sw[b][k], p[k], acc2);
            po[b] = acc2;
        }
        size_t off = (((size_t)(n * 64 + c) * (4 * HH) + 4 * h + a) * (size_t)(4 * WW)) +
                     4 * (w0 + wl);
        *reinterpret_cast<float4*>(out + off) = ov;
    }
}

extern "C" void kernel_launch(void* const* d_in, const int* in_sizes, int n_in,
                              void* d_out, int out_size) {
    const float* x   = (const float*)d_in[0];
    const float* f1  = (const float*)d_in[1];
    const float* w1  = (const float*)d_in[2];
    const float* b1  = (const float*)d_in[3];
    const float* w2  = (const float*)d_in[4];
    const float* b2  = (const float*)d_in[5];
    const float* gw1 = (const float*)d_in[6];
    const float* gb1 = (const float*)d_in[7];
    const float* gw2 = (const float*)d_in[8];
    const float* gb2 = (const float*)d_in[9];
    float* out = (float*)d_out;

    const int N = in_sizes[0] / (64 * HH * WW);

    float *p_gw1t = nullptr, *p_segmid = nullptr, *p_seg = nullptr, *p_g = nullptr,
          *p_wts = nullptr;
    cudaGetSymbolAddress((void**)&p_gw1t, d_gw1t);
    cudaGetSymbolAddress((void**)&p_segmid, d_seg_mid);
    cudaGetSymbolAddress((void**)&p_seg, d_seg);
    cudaGetSymbolAddress((void**)&p_g, d_g);
    cudaGetSymbolAddress((void**)&p_wts, d_wts);

    // no static guards allowed: set the attribute unconditionally (cheap, capture-safe)
    cudaFuncSetAttribute(guidance_mma_kernel,
                         cudaFuncAttributeMaxDynamicSharedMemorySize, GUID_SMEM);

    // 1. fold redundant concat + transpose + tf32-round the guidance weights
    fold_gw1_kernel<<<(9 * 256 * 256 + 255) / 256, 256>>>(gw1);
    // 2. seg branch (fp32 direct)
    conv3x3_kernel<64, 32, true><<<dim3(WW / 32, HH / 32, N * (32 / 8)), 256>>>(x, w1, b1, p_segmid);
    conv3x3_kernel<32, 64, false><<<dim3(WW / 32, HH / 32, N * (64 / 8)), 256>>>(p_segmid, w2, b2, p_seg);
    // 3. guidance conv3x3 256->256 + relu: tf32 tensor cores
    guidance_mma_kernel<<<dim3(HH / 2, 2, N), 256, GUID_SMEM>>>(f1, p_gw1t, gb1, p_g);
    // 4. conv1x1 256->144 (logits)
    conv1x1_kernel<256, 144><<<dim3(WW / 32, HH / 32, N * (144 / 8)), 256>>>(p_g, gw2, gb2, p_wts);
    // 5. softmax + convex combine + pixel shuffle
    combine_kernel<<<dim3(WW / 32, HH, N), 128>>>(p_wts, p_seg, out);
}